// round 6
// baseline (speedup 1.0000x reference)
#include <cuda_runtime.h>
#include <math.h>
#include <stdint.h>

#define N_SEQ   2048
#define SEQ_LEN 24
#define SEQ_C   9
#define N_FILT  32
#define KM      16
#define HID     128
#define NCLS    10

#define KPAD 33                 // padded filter stride (conflict-free smem)
#define SEQS_PER_BLK 8

__device__ float g_feats[N_SEQ * N_FILT];

__device__ __forceinline__ void cp_async16(uint32_t saddr, const void* gptr) {
    asm volatile("cp.async.cg.shared.global [%0], [%1], 16;" :: "r"(saddr), "l"(gptr));
}
__device__ __forceinline__ void cp_async_commit() {
    asm volatile("cp.async.commit_group;");
}
__device__ __forceinline__ void cp_async_wait_all() {
    asm volatile("cp.async.wait_group 0;");
}

// ---------------------------------------------------------------------------
// DTW: 256 threads = 8 warps, warp = sequence, lane = filter. SCALAR math
// (round-2 proven-fast inner loop), kernels staged into padded smem
// (coalesced loads, conflict-free reads). Forward DP == backtracked path sum.
// ---------------------------------------------------------------------------
__global__ __launch_bounds__(256) void dtw_kernel(const float* __restrict__ x,
                                                  const float* __restrict__ kernels) {
    __shared__ float kTS[KM * SEQ_C * KPAD];           // [i*9+c][f] padded
    __shared__ float knS[KM * N_FILT];                 // |k_i|^2  [i][f]
    __shared__ float seqS[SEQS_PER_BLK][SEQ_LEN * SEQ_C];
    __shared__ float snS[SEQS_PER_BLK][SEQ_LEN];       // |s_j|^2

    const int t   = threadIdx.x;
    const int wid = t >> 5;
    const int f   = t & 31;
    const int s   = blockIdx.x * SEQS_PER_BLK + wid;

    // Stage kernels transposed (coalesced global reads, padded smem stores)
    for (int idx = t; idx < N_FILT * KM * SEQ_C; idx += 256) {
        int fk  = idx / (KM * SEQ_C);
        int rem = idx - fk * (KM * SEQ_C);      // i*9 + c
        kTS[rem * KPAD + fk] = kernels[idx];
    }
    // Stage this warp's sequence (216 contiguous floats)
    {
        const float* xs = x + s * (SEQ_LEN * SEQ_C);
        for (int i = f; i < SEQ_LEN * SEQ_C; i += 32) seqS[wid][i] = xs[i];
    }
    __syncthreads();

    // Kernel-row norms (cooperative) and sequence-column norms (per warp)
    for (int idx = t; idx < KM * N_FILT; idx += 256) {
        int i = idx >> 5, ff = idx & 31;
        float a = 0.f;
#pragma unroll
        for (int c = 0; c < SEQ_C; ++c) {
            float v = kTS[(i * SEQ_C + c) * KPAD + ff];
            a = fmaf(v, v, a);
        }
        knS[idx] = a;
    }
    if (f < SEQ_LEN) {
        float a = 0.f;
#pragma unroll
        for (int c = 0; c < SEQ_C; ++c) {
            float v = seqS[wid][f * SEQ_C + c];
            a = fmaf(v, v, a);
        }
        snS[wid][f] = a;
    }
    __syncthreads();

    float Dp[SEQ_LEN];

    // ---- Row 0: cumulative sum of C[0][j] ----
    {
        float kv[SEQ_C];
#pragma unroll
        for (int c = 0; c < SEQ_C; ++c) kv[c] = kTS[c * KPAD + f];
        float kn = knS[f];
        float run = 0.f;
#pragma unroll
        for (int j = 0; j < SEQ_LEN; ++j) {
            float dot = 0.f;
#pragma unroll
            for (int c = 0; c < SEQ_C; ++c) dot = fmaf(kv[c], seqS[wid][j * SEQ_C + c], dot);
            float Cv = fmaf(-2.f, dot, kn + snS[wid][j]);
            run = (j == 0) ? Cv : (run + Cv);
            Dp[j] = run;
        }
    }

    const float INF = __int_as_float(0x7f800000);

    // ---- Rows 1..15 in 3 sweeps of 5 ----
    for (int sw = 0; sw < 3; ++sw) {
        const int i0 = 1 + sw * 5;
        float kr[5][SEQ_C], knr[5], left[5];
#pragma unroll
        for (int r = 0; r < 5; ++r) {
#pragma unroll
            for (int c = 0; c < SEQ_C; ++c)
                kr[r][c] = kTS[((i0 + r) * SEQ_C + c) * KPAD + f];
            knr[r] = knS[(i0 + r) * N_FILT + f];
            left[r] = INF;
        }
        float diagc = INF;
#pragma unroll
        for (int j = 0; j < SEQ_LEN; ++j) {
            float sv[SEQ_C];
#pragma unroll
            for (int c = 0; c < SEQ_C; ++c) sv[c] = seqS[wid][j * SEQ_C + c];
            float sn = snS[wid][j];
            float up = Dp[j];
            float oldup = up;
            float diag = diagc;
#pragma unroll
            for (int r = 0; r < 5; ++r) {
                float dot = 0.f;
#pragma unroll
                for (int c = 0; c < SEQ_C; ++c) dot = fmaf(kr[r][c], sv[c], dot);
                float Cv = fmaf(-2.f, dot, knr[r] + sn);
                float best = fminf(left[r], fminf(up, diag));
                float d = Cv + best;
                diag = left[r];
                left[r] = d;
                up = d;
            }
            Dp[j] = up;
            diagc = oldup;
        }
    }

    g_feats[s * N_FILT + f] = Dp[SEQ_LEN - 1];
}

// ---------------------------------------------------------------------------
// MLP: 256 threads, 8 seqs/block. W2 (64KB) prefetched into smem via cp.async
// overlapped with layer-1 compute; Wl staged transposed. Thread = (hu, half):
// hu = hidden unit, half selects which 4 sequences. No reduction-split -> only
// 3 barriers. Dynamic smem (~80KB).
// ---------------------------------------------------------------------------
__global__ __launch_bounds__(256) void mlp_kernel(
    const float* __restrict__ W1, const float* __restrict__ b1,
    const float* __restrict__ W2, const float* __restrict__ b2,
    const float* __restrict__ Wl, const float* __restrict__ bl,
    float* __restrict__ out) {
    extern __shared__ float smem[];
    float* W2s = smem;                       // [HID*HID]           64KB
    float* t1S = W2s + HID * HID;            // [h][8 seqs]          4KB
    float* t2S = t1S + HID * 8;              // [h][8 seqs]          4KB
    float* fSt = t2S + HID * 8;              // [filter][8 seqs]     1KB
    float* WlS = fSt + N_FILT * 8;           // [c][h] transposed    5KB

    const int t    = threadIdx.x;
    const int hu   = t & 127;
    const int half = t >> 7;
    const int s0   = blockIdx.x * 8;

    // Prefetch W2 into smem (async, no registers): 16 x 16B per thread
    {
        uint32_t base = (uint32_t)__cvta_generic_to_shared(W2s);
        const float4* g = reinterpret_cast<const float4*>(W2);
#pragma unroll
        for (int i = 0; i < 16; ++i) {
            int e = t + i * 256;             // float4 index
            cp_async16(base + e * 16, g + e);
        }
        cp_async_commit();
    }

    // Stage features transposed [filter][seq] and Wl transposed [c][h]
    fSt[(t & 31) * 8 + (t >> 5)] = g_feats[s0 * N_FILT + t];
    for (int i = t; i < HID * NCLS; i += 256) {
        int h = i / NCLS, c = i - h * NCLS;
        WlS[c * HID + h] = Wl[i];
    }
    __syncthreads();   // fSt, WlS visible (W2 still in flight)

    // ---- Layer 1 (32 -> 128): half does seqs half*4..+3; W1 from global ----
    {
        float b = b1[hu];
        float a0 = b, a1 = b, a2 = b, a3 = b;
#pragma unroll
        for (int ff = 0; ff < N_FILT; ++ff) {
            float w = W1[ff * HID + hu];
            float4 v = *reinterpret_cast<const float4*>(&fSt[ff * 8 + half * 4]);
            a0 = fmaf(v.x, w, a0);
            a1 = fmaf(v.y, w, a1);
            a2 = fmaf(v.z, w, a2);
            a3 = fmaf(v.w, w, a3);
        }
        float4 r = make_float4(fmaxf(a0, 0.f), fmaxf(a1, 0.f),
                               fmaxf(a2, 0.f), fmaxf(a3, 0.f));
        *reinterpret_cast<float4*>(&t1S[hu * 8 + half * 4]) = r;
    }
    cp_async_wait_all();
    __syncthreads();   // t1S + W2s ready

    // ---- Layer 2 (128 -> 128): all operands in smem ----
    {
        float c0 = 0.f, c1 = 0.f, c2 = 0.f, c3 = 0.f;
#pragma unroll 16
        for (int h = 0; h < HID; ++h) {
            float w = W2s[h * HID + hu];
            float4 v = *reinterpret_cast<const float4*>(&t1S[h * 8 + half * 4]);
            c0 = fmaf(v.x, w, c0);
            c1 = fmaf(v.y, w, c1);
            c2 = fmaf(v.z, w, c2);
            c3 = fmaf(v.w, w, c3);
        }
        float b = b2[hu];
        float4 r = make_float4(fmaxf(c0 + b, 0.f), fmaxf(c1 + b, 0.f),
                               fmaxf(c2 + b, 0.f), fmaxf(c3 + b, 0.f));
        *reinterpret_cast<float4*>(&t2S[hu * 8 + half * 4]) = r;
    }
    __syncthreads();

    // ---- Logits + softmax: warp w handles sequence s0 + w ----
    const int wid  = t >> 5;
    const int lane = t & 31;
    float acc[NCLS];
#pragma unroll
    for (int c = 0; c < NCLS; ++c) acc[c] = 0.f;
#pragma unroll
    for (int q = 0; q < 4; ++q) {
        int h = lane + q * 32;
        float v = t2S[h * 8 + wid];
#pragma unroll
        for (int c = 0; c < NCLS; ++c) acc[c] = fmaf(v, WlS[c * HID + h], acc[c]);
    }
#pragma unroll
    for (int off = 16; off > 0; off >>= 1) {
#pragma unroll
        for (int c = 0; c < NCLS; ++c)
            acc[c] += __shfl_xor_sync(0xffffffffu, acc[c], off);
    }
    if (lane == 0) {
        float mx = -__int_as_float(0x7f800000);
#pragma unroll
        for (int c = 0; c < NCLS; ++c) {
            acc[c] += bl[c];
            mx = fmaxf(mx, acc[c]);
        }
        float e[NCLS];
        float sum = 0.f;
#pragma unroll
        for (int c = 0; c < NCLS; ++c) {
            e[c] = __expf(acc[c] - mx);
            sum += e[c];
        }
        float inv = 1.f / sum;
#pragma unroll
        for (int c = 0; c < NCLS; ++c)
            out[(s0 + wid) * NCLS + c] = e[c] * inv;
    }
}

#define MLP_SMEM ((HID * HID + HID * 8 + HID * 8 + N_FILT * 8 + HID * NCLS) * 4)

extern "C" void kernel_launch(void* const* d_in, const int* in_sizes, int n_in,
                              void* d_out, int out_size) {
    const float* x       = (const float*)d_in[0];
    const float* kernels = (const float*)d_in[1];
    const float* W1      = (const float*)d_in[2];
    const float* b1      = (const float*)d_in[3];
    const float* W2      = (const float*)d_in[4];
    const float* b2      = (const float*)d_in[5];
    const float* Wl      = (const float*)d_in[6];
    const float* bl      = (const float*)d_in[7];
    float* out = (float*)d_out;

    cudaFuncSetAttribute(mlp_kernel, cudaFuncAttributeMaxDynamicSharedMemorySize, MLP_SMEM);

    dtw_kernel<<<N_SEQ / SEQS_PER_BLK, 256>>>(x, kernels);
    mlp_kernel<<<N_SEQ / 8, 256, MLP_SMEM>>>(W1, b1, W2, b2, Wl, bl, out);
}

// round 7
// speedup vs baseline: 1.8442x; 1.8442x over previous
#include <cuda_runtime.h>
#include <math.h>
#include <stdint.h>

#define N_SEQ   2048
#define SEQ_LEN 24
#define SEQ_C   9
#define N_FILT  32
#define KM      16
#define HID     128
#define NCLS    10

__device__ float g_kT[KM * SEQ_C * N_FILT];   // kernels transposed: [i][c][f]
__device__ float g_knorm[KM * N_FILT];        // |kernel row|^2:    [i][f]
__device__ float g_feats[N_SEQ * N_FILT];     // DTW features

__device__ __forceinline__ void cp_async16(uint32_t saddr, const void* gptr) {
    asm volatile("cp.async.cg.shared.global [%0], [%1], 16;" :: "r"(saddr), "l"(gptr));
}
__device__ __forceinline__ void cp_async_commit() {
    asm volatile("cp.async.commit_group;");
}
__device__ __forceinline__ void cp_async_wait_all() {
    asm volatile("cp.async.wait_group 0;");
}

// ---------------------------------------------------------------------------
// Kernel 1: transpose kernels to [i][c][f] + row norms. (r2 verbatim)
// ---------------------------------------------------------------------------
__global__ void prep_kernel(const float* __restrict__ kernels) {
    int idx = blockIdx.x * blockDim.x + threadIdx.x;
    if (idx >= KM * N_FILT) return;
    int i = idx >> 5;
    int f = idx & 31;
    float nrm = 0.f;
#pragma unroll
    for (int c = 0; c < SEQ_C; ++c) {
        float v = kernels[f * (KM * SEQ_C) + i * SEQ_C + c];
        g_kT[(i * SEQ_C + c) * N_FILT + f] = v;
        nrm = fmaf(v, v, nrm);
    }
    g_knorm[i * N_FILT + f] = nrm;
}

// ---------------------------------------------------------------------------
// Kernel 2: DTW forward DP. One warp per block/sequence, lane = filter.
// (r2 verbatim — measured ~10us) Forward DP == backtracked path-cost sum.
// ---------------------------------------------------------------------------
__global__ __launch_bounds__(32) void dtw_kernel(const float* __restrict__ x) {
    __shared__ float seqS[SEQ_LEN * SEQ_C];
    __shared__ float snormS[SEQ_LEN];

    const int s = blockIdx.x;
    const int f = threadIdx.x;

    const float* xs = x + s * (SEQ_LEN * SEQ_C);
    for (int t = f; t < SEQ_LEN * SEQ_C; t += 32) seqS[t] = xs[t];
    __syncthreads();

    if (f < SEQ_LEN) {
        float a = 0.f;
#pragma unroll
        for (int c = 0; c < SEQ_C; ++c) {
            float v = seqS[f * SEQ_C + c];
            a = fmaf(v, v, a);
        }
        snormS[f] = a;
    }
    __syncthreads();

    float Dp[SEQ_LEN];

    // Row 0: cumsum of C[0][j]
    {
        float k0[SEQ_C];
#pragma unroll
        for (int c = 0; c < SEQ_C; ++c) k0[c] = g_kT[c * N_FILT + f];
        float kn = g_knorm[f];
        float run = 0.f;
#pragma unroll
        for (int j = 0; j < SEQ_LEN; ++j) {
            float dot = 0.f;
#pragma unroll
            for (int c = 0; c < SEQ_C; ++c) dot = fmaf(k0[c], seqS[j * SEQ_C + c], dot);
            float Cv = fmaf(-2.f, dot, kn + snormS[j]);
            run = (j == 0) ? Cv : (run + Cv);
            Dp[j] = run;
        }
    }

    const float INF = __int_as_float(0x7f800000);

    // Rows 1..15 in 3 sweeps of 5
    for (int sw = 0; sw < 3; ++sw) {
        const int i0 = 1 + sw * 5;
        float kr[5][SEQ_C], knr[5], left[5];
#pragma unroll
        for (int r = 0; r < 5; ++r) {
#pragma unroll
            for (int c = 0; c < SEQ_C; ++c)
                kr[r][c] = g_kT[((i0 + r) * SEQ_C + c) * N_FILT + f];
            knr[r] = g_knorm[(i0 + r) * N_FILT + f];
            left[r] = INF;
        }
        float diagc = INF;
#pragma unroll
        for (int j = 0; j < SEQ_LEN; ++j) {
            float sv[SEQ_C];
#pragma unroll
            for (int c = 0; c < SEQ_C; ++c) sv[c] = seqS[j * SEQ_C + c];
            float sn = snormS[j];
            float up = Dp[j];
            float oldup = up;
            float diag = diagc;
#pragma unroll
            for (int r = 0; r < 5; ++r) {
                float dot = 0.f;
#pragma unroll
                for (int c = 0; c < SEQ_C; ++c) dot = fmaf(kr[r][c], sv[c], dot);
                float Cv = fmaf(-2.f, dot, knr[r] + sn);
                float best = fminf(left[r], fminf(up, diag));
                float d = Cv + best;
                diag = left[r];
                left[r] = d;
                up = d;
            }
            Dp[j] = up;
            diagc = oldup;
        }
    }

    g_feats[s * N_FILT + f] = Dp[SEQ_LEN - 1];
}

// ---------------------------------------------------------------------------
// Kernel 3: MLP (r6 verbatim — measured 12.5us). 256 threads, 8 seqs/block,
// W2 cp.async into smem overlapped with layer 1; Wl staged transposed.
// ---------------------------------------------------------------------------
__global__ __launch_bounds__(256) void mlp_kernel(
    const float* __restrict__ W1, const float* __restrict__ b1,
    const float* __restrict__ W2, const float* __restrict__ b2,
    const float* __restrict__ Wl, const float* __restrict__ bl,
    float* __restrict__ out) {
    extern __shared__ float smem[];
    float* W2s = smem;                       // [HID*HID]           64KB
    float* t1S = W2s + HID * HID;            // [h][8 seqs]          4KB
    float* t2S = t1S + HID * 8;              // [h][8 seqs]          4KB
    float* fSt = t2S + HID * 8;              // [filter][8 seqs]     1KB
    float* WlS = fSt + N_FILT * 8;           // [c][h] transposed    5KB

    const int t    = threadIdx.x;
    const int hu   = t & 127;
    const int half = t >> 7;
    const int s0   = blockIdx.x * 8;

    {
        uint32_t base = (uint32_t)__cvta_generic_to_shared(W2s);
        const float4* g = reinterpret_cast<const float4*>(W2);
#pragma unroll
        for (int i = 0; i < 16; ++i) {
            int e = t + i * 256;
            cp_async16(base + e * 16, g + e);
        }
        cp_async_commit();
    }

    fSt[(t & 31) * 8 + (t >> 5)] = g_feats[s0 * N_FILT + t];
    for (int i = t; i < HID * NCLS; i += 256) {
        int h = i / NCLS, c = i - h * NCLS;
        WlS[c * HID + h] = Wl[i];
    }
    __syncthreads();

    {
        float b = b1[hu];
        float a0 = b, a1 = b, a2 = b, a3 = b;
#pragma unroll
        for (int ff = 0; ff < N_FILT; ++ff) {
            float w = W1[ff * HID + hu];
            float4 v = *reinterpret_cast<const float4*>(&fSt[ff * 8 + half * 4]);
            a0 = fmaf(v.x, w, a0);
            a1 = fmaf(v.y, w, a1);
            a2 = fmaf(v.z, w, a2);
            a3 = fmaf(v.w, w, a3);
        }
        float4 r = make_float4(fmaxf(a0, 0.f), fmaxf(a1, 0.f),
                               fmaxf(a2, 0.f), fmaxf(a3, 0.f));
        *reinterpret_cast<float4*>(&t1S[hu * 8 + half * 4]) = r;
    }
    cp_async_wait_all();
    __syncthreads();

    {
        float c0 = 0.f, c1 = 0.f, c2 = 0.f, c3 = 0.f;
#pragma unroll 16
        for (int h = 0; h < HID; ++h) {
            float w = W2s[h * HID + hu];
            float4 v = *reinterpret_cast<const float4*>(&t1S[h * 8 + half * 4]);
            c0 = fmaf(v.x, w, c0);
            c1 = fmaf(v.y, w, c1);
            c2 = fmaf(v.z, w, c2);
            c3 = fmaf(v.w, w, c3);
        }
        float b = b2[hu];
        float4 r = make_float4(fmaxf(c0 + b, 0.f), fmaxf(c1 + b, 0.f),
                               fmaxf(c2 + b, 0.f), fmaxf(c3 + b, 0.f));
        *reinterpret_cast<float4*>(&t2S[hu * 8 + half * 4]) = r;
    }
    __syncthreads();

    const int wid  = t >> 5;
    const int lane = t & 31;
    float acc[NCLS];
#pragma unroll
    for (int c = 0; c < NCLS; ++c) acc[c] = 0.f;
#pragma unroll
    for (int q = 0; q < 4; ++q) {
        int h = lane + q * 32;
        float v = t2S[h * 8 + wid];
#pragma unroll
        for (int c = 0; c < NCLS; ++c) acc[c] = fmaf(v, WlS[c * HID + h], acc[c]);
    }
#pragma unroll
    for (int off = 16; off > 0; off >>= 1) {
#pragma unroll
        for (int c = 0; c < NCLS; ++c)
            acc[c] += __shfl_xor_sync(0xffffffffu, acc[c], off);
    }
    if (lane == 0) {
        float mx = -__int_as_float(0x7f800000);
#pragma unroll
        for (int c = 0; c < NCLS; ++c) {
            acc[c] += bl[c];
            mx = fmaxf(mx, acc[c]);
        }
        float e[NCLS];
        float sum = 0.f;
#pragma unroll
        for (int c = 0; c < NCLS; ++c) {
            e[c] = __expf(acc[c] - mx);
            sum += e[c];
        }
        float inv = 1.f / sum;
#pragma unroll
        for (int c = 0; c < NCLS; ++c)
            out[(s0 + wid) * NCLS + c] = e[c] * inv;
    }
}

#define MLP_SMEM ((HID * HID + HID * 8 + HID * 8 + N_FILT * 8 + HID * NCLS) * 4)

extern "C" void kernel_launch(void* const* d_in, const int* in_sizes, int n_in,
                              void* d_out, int out_size) {
    const float* x       = (const float*)d_in[0];
    const float* kernels = (const float*)d_in[1];
    const float* W1      = (const float*)d_in[2];
    const float* b1      = (const float*)d_in[3];
    const float* W2      = (const float*)d_in[4];
    const float* b2      = (const float*)d_in[5];
    const float* Wl      = (const float*)d_in[6];
    const float* bl      = (const float*)d_in[7];
    float* out = (float*)d_out;

    cudaFuncSetAttribute(mlp_kernel, cudaFuncAttributeMaxDynamicSharedMemorySize, MLP_SMEM);

    prep_kernel<<<1, 512>>>(kernels);
    dtw_kernel<<<N_SEQ, 32>>>(x);
    mlp_kernel<<<N_SEQ / 8, 256, MLP_SMEM>>>(W1, b1, W2, b2, Wl, bl, out);
}